// round 5
// baseline (speedup 1.0000x reference)
#include <cuda_runtime.h>
#include <cstdint>

#define BATCHN 1024
#define NIMG   2048
#define T_STRIDE 132

// ---- smem layout (bytes) ----
#define SM_Z0   0           // 2 x 65536 z buffers
#define SM_FY   131072      // 64x128 f32 (gamma folded)
#define SM_T    163840      // 64 x 132 f32 (padded)
#define SM_FXT  197632      // 128x64 f32 (F_X transposed)
#define SM_MBAR 230400      // 2 mbarriers
#define SMEM_TOTAL 230416

__device__ float g_FY[64 * 128];    // F_Y normalized, gamma folded
__device__ float g_FXT[128 * 64];   // F_X[m][b] stored as [b][m]

// ======================= setup kernel =======================
__global__ void setup_kernel(const float* __restrict__ hrow,
                             const float* __restrict__ W,
                             const float* __restrict__ bias) {
    __shared__ float red[256];
    __shared__ float sc[8];
    int tid = threadIdx.x;

    // params[j] = h[0] . W[j] + b[j]
    for (int j = 0; j < 5; j++) {
        float s = 0.f;
        for (int k = tid; k < 1024; k += 256) s += hrow[k] * W[j * 1024 + k];
        red[tid] = s; __syncthreads();
        for (int o = 128; o > 0; o >>= 1) { if (tid < o) red[tid] += red[tid + o]; __syncthreads(); }
        if (tid == 0) sc[j] = red[0] + bias[j];
        __syncthreads();
    }

    if (tid == 0) {
        float gtX = sc[0], gtY = sc[1], log_var = sc[2], log_dt = sc[3], lg = sc[4];
        sc[0] = 129.f * (gtX + 1.f) * 0.5f;          // g_X
        sc[1] = 129.f * (gtY + 1.f) * 0.5f;          // g_Y
        sc[2] = expf(log_var + 1e-8f);               // var
        sc[3] = expf(log_dt) * (127.f / 63.f);       // d
        sc[4] = expf(lg);                            // gamma
    }
    __syncthreads();
    float gX = sc[0], gY = sc[1], var = sc[2], dd = sc[3], gamma = sc[4];

    // F_Y (uses mu_Y) -> g_FY[n*128+c], accumulate global sum
    float partY = 0.f;
    for (int idx = tid; idx < 8192; idx += 256) {
        int n = idx >> 7, c = idx & 127;
        float mu = gY + ((float)n - 32.5f) * dd;
        float df = (float)c - mu;
        float e = expf(-(df * df) / (2.0f * var));
        g_FY[idx] = e; partY += e;
    }
    red[tid] = partY; __syncthreads();
    for (int o = 128; o > 0; o >>= 1) { if (tid < o) red[tid] += red[tid + o]; __syncthreads(); }
    if (tid == 0) sc[5] = red[0];
    __syncthreads();

    // F_X (uses mu_X), stored transposed g_FXT[c*64+m]
    float partX = 0.f;
    for (int idx = tid; idx < 8192; idx += 256) {
        int m = idx >> 7, c = idx & 127;
        float mu = gX + ((float)m - 32.5f) * dd;
        float df = (float)c - mu;
        float e = expf(-(df * df) / (2.0f * var));
        g_FXT[c * 64 + m] = e; partX += e;
    }
    red[tid] = partX; __syncthreads();
    for (int o = 128; o > 0; o >>= 1) { if (tid < o) red[tid] += red[tid + o]; __syncthreads(); }
    if (tid == 0) sc[6] = red[0];
    __syncthreads();

    float sY = gamma / sc[5];
    float sX = 1.0f / sc[6];
    for (int idx = tid; idx < 8192; idx += 256) {
        g_FY[idx]  *= sY;
        g_FXT[idx] *= sX;
    }
}

// ======================= helpers =======================
__device__ __forceinline__ uint32_t smem_u32(const void* p) {
    uint32_t a;
    asm("{ .reg .u64 t; cvta.to.shared.u64 t, %1; cvt.u32.u64 %0, t; }" : "=r"(a) : "l"(p));
    return a;
}
__device__ __forceinline__ unsigned long long dup2(float f) {
    unsigned long long r;
    asm("mov.b64 %0, {%1, %1};" : "=l"(r) : "f"(f));
    return r;
}
__device__ __forceinline__ void fma2(unsigned long long& c, unsigned long long a, unsigned long long b) {
    asm("fma.rn.f32x2 %0, %1, %2, %0;" : "+l"(c) : "l"(a), "l"(b));
}
__device__ __forceinline__ void mbar_wait(uint32_t addr, uint32_t parity) {
    asm volatile(
        "{\n\t.reg .pred P;\n\t"
        "LAB_%=:\n\t"
        "mbarrier.try_wait.parity.acquire.cta.shared::cta.b64 P, [%0], %1, 0x989680;\n\t"
        "@P bra.uni DONE_%=;\n\t"
        "bra.uni LAB_%=;\n\t"
        "DONE_%=:\n\t}"
        :: "r"(addr), "r"(parity) : "memory");
}
__device__ __forceinline__ void bulk_load(uint32_t dst, const float* src, uint32_t mbar) {
    asm volatile("mbarrier.arrive.expect_tx.shared.b64 _, [%0], %1;"
                 :: "r"(mbar), "r"(65536u) : "memory");
    asm volatile("cp.async.bulk.shared::cta.global.mbarrier::complete_tx::bytes [%0], [%1], %2, [%3];"
                 :: "r"(dst), "l"(src), "r"(65536u), "r"(mbar) : "memory");
}

// ======================= main kernel =======================
__global__ void __launch_bounds__(256, 1)
main_kernel(const float* __restrict__ x, const float* __restrict__ xh,
            float* __restrict__ out, int grid) {
    extern __shared__ __align__(16) char smem[];
    float* sFY  = (float*)(smem + SM_FY);
    float* sT   = (float*)(smem + SM_T);
    float* sFXT = (float*)(smem + SM_FXT);
    int tid = threadIdx.x;

    // stage filters into smem
    for (int i = tid; i < 8192; i += 256) { sFY[i] = g_FY[i]; sFXT[i] = g_FXT[i]; }

    uint32_t mb  = smem_u32(smem + SM_MBAR);
    uint32_t zsm = smem_u32(smem);
    if (tid == 0) {
        asm volatile("mbarrier.init.shared.b64 [%0], 1;" :: "r"(mb));
        asm volatile("mbarrier.init.shared.b64 [%0], 1;" :: "r"(mb + 8));
        asm volatile("fence.proxy.async.shared::cta;" ::: "memory");
    }
    __syncthreads();

    int img0 = blockIdx.x;
    if (tid == 0 && img0 < NIMG) {
        const float* src = (img0 < BATCHN) ? x + (size_t)img0 * 16384
                                           : xh + (size_t)(img0 - BATCHN) * 16384;
        bulk_load(zsm, src, mb);
    }

    const int bx = tid & 15, ny = tid >> 4;   // stage-1 map
    const int g  = tid & 7,  nh = tid >> 3;   // stage-2 map

    int it = 0;
    for (int img = img0; img < NIMG; img += grid, it++) {
        int buf = it & 1;

        // prefetch next image into other buffer (its last reader synced at it-1)
        int nxt = img + grid;
        if (tid == 0 && nxt < NIMG) {
            const float* src = (nxt < BATCHN) ? x + (size_t)nxt * 16384
                                              : xh + (size_t)(nxt - BATCHN) * 16384;
            bulk_load(zsm + (buf ^ 1) * 65536u, src, mb + (buf ^ 1) * 8);
        }

        // wait for this buffer's data
        mbar_wait(mb + buf * 8, (uint32_t)((it >> 1) & 1));

        const char* zb = smem + buf * 65536;

        // ---- stage 1: t[n][b] = sum_a FY[n][a] * z[a][b]  (f32x2 over b) ----
        unsigned long long acc[4][4];
#pragma unroll
        for (int i = 0; i < 4; i++)
#pragma unroll
            for (int j = 0; j < 4; j++) acc[i][j] = 0ull;

#pragma unroll 4
        for (int a = 0; a < 128; a++) {
            const unsigned long long* zr = (const unsigned long long*)(zb + a * 512);
            unsigned long long z0 = zr[bx], z1 = zr[bx + 16], z2 = zr[bx + 32], z3 = zr[bx + 48];
#pragma unroll
            for (int i = 0; i < 4; i++) {
                unsigned long long f = dup2(sFY[(ny * 4 + i) * 128 + a]);
                fma2(acc[i][0], f, z0);
                fma2(acc[i][1], f, z1);
                fma2(acc[i][2], f, z2);
                fma2(acc[i][3], f, z3);
            }
        }
#pragma unroll
        for (int i = 0; i < 4; i++)
#pragma unroll
            for (int j = 0; j < 4; j++) {
                int n = ny * 4 + i, bp = bx + 16 * j;
                *(unsigned long long*)(sT + n * T_STRIDE + 2 * bp) = acc[i][j];
            }
        __syncthreads();

        // ---- stage 2: out[n][m] = sum_b t[n][b] * FXT[b][m]  (f32x2 over m) ----
        unsigned long long acc2[2][4];
#pragma unroll
        for (int i = 0; i < 2; i++)
#pragma unroll
            for (int j = 0; j < 4; j++) acc2[i][j] = 0ull;

#pragma unroll 4
        for (int b = 0; b < 128; b++) {
            const unsigned long long* fr = (const unsigned long long*)(sFXT + b * 64);
            unsigned long long f0 = fr[g], f1 = fr[g + 8], f2 = fr[g + 16], f3 = fr[g + 24];
#pragma unroll
            for (int i = 0; i < 2; i++) {
                unsigned long long tdup = dup2(sT[(nh * 2 + i) * T_STRIDE + b]);
                fma2(acc2[i][0], tdup, f0);
                fma2(acc2[i][1], tdup, f1);
                fma2(acc2[i][2], tdup, f2);
                fma2(acc2[i][3], tdup, f3);
            }
        }

        size_t obase = (img < BATCHN) ? (size_t)img * 8192
                                      : (size_t)(img - BATCHN) * 8192 + 4096;
        float* op = out + obase;
#pragma unroll
        for (int i = 0; i < 2; i++)
#pragma unroll
            for (int j = 0; j < 4; j++) {
                int n = nh * 2 + i, m = 2 * g + 16 * j;
                *(unsigned long long*)(op + n * 64 + m) = acc2[i][j];
            }
        __syncthreads();   // t / z[buf] reuse safety for next iteration
    }
}

// ======================= launch =======================
extern "C" void kernel_launch(void* const* d_in, const int* in_sizes, int n_in,
                              void* d_out, int out_size) {
    const float* x  = (const float*)d_in[0];
    const float* xh = (const float*)d_in[1];
    const float* h  = (const float*)d_in[2];
    const float* W  = (const float*)d_in[3];
    const float* b  = (const float*)d_in[4];
    float* out = (float*)d_out;

    setup_kernel<<<1, 256>>>(h, W, b);

    cudaFuncSetAttribute(main_kernel, cudaFuncAttributeMaxDynamicSharedMemorySize, SMEM_TOTAL);

    int dev = 0, sm = 148;
    cudaGetDevice(&dev);
    cudaDeviceGetAttribute(&sm, cudaDevAttrMultiProcessorCount, dev);
    int grid = sm;
    if (grid < 1) grid = 148;
    if (grid > NIMG) grid = NIMG;

    main_kernel<<<grid, 256, SMEM_TOTAL>>>(x, xh, out, grid);
}